// round 1
// baseline (speedup 1.0000x reference)
#include <cuda_runtime.h>
#include <math.h>
#include <stdint.h>

#define N_NODES 50000
#define N_EDGES 1600000
#define G 128
#define LG 16

#define PI_F 3.14159265358979323846f

// ---- scratch (device globals; no allocation allowed) ----
__device__ __align__(16) float g_a[N_NODES * LG];        // n_s @ en_w[0:16]
__device__ __align__(16) float g_b[N_NODES * LG];        // n_s @ en_w[16:32] + en_b
__device__ __align__(16) float g_nv[N_NODES * 3 * LG];   // node_v @ nv_in_w
__device__ __align__(16) float g_acc_s[N_NODES * LG];    // segment sums
__device__ __align__(16) float g_acc_v[N_NODES * 3 * LG];

__device__ __forceinline__ float siluf(float x) { return x / (1.f + __expf(-x)); }

__device__ __forceinline__ void red4(float* p, float a, float b, float c, float d) {
    asm volatile("red.global.add.v4.f32 [%0], {%1,%2,%3,%4};"
                 :: "l"(p), "f"(a), "f"(b), "f"(c), "f"(d) : "memory");
}

// ============================================================================
// Kernel 1: per-node input projections + en_w pre-split + accumulator zeroing
// one block (128 threads) per node
// ============================================================================
__global__ void __launch_bounds__(128) k_node_in(
    const float* __restrict__ node_s, const float* __restrict__ node_v,
    const float* __restrict__ ns_w, const float* __restrict__ ns_b,
    const float* __restrict__ nv_w, const float* __restrict__ en_w,
    const float* __restrict__ en_b)
{
    int n = blockIdx.x;
    int t = threadIdx.x;  // 128
    __shared__ float ss[G];
    __shared__ float sv[3 * G];
    __shared__ float sns[LG];

    ss[t] = node_s[(size_t)n * G + t];
    sv[t]           = node_v[(size_t)n * 3 * G + t];
    sv[t + G]       = node_v[(size_t)n * 3 * G + G + t];
    sv[t + 2 * G]   = node_v[(size_t)n * 3 * G + 2 * G + t];
    __syncthreads();

    if (t < LG) {
        float acc = ns_b[t];
        #pragma unroll 8
        for (int l = 0; l < G; l++) acc += ss[l] * ns_w[l * LG + t];
        sns[t] = siluf(acc);
    } else if (t < 64) {
        int j = t - LG; int x = j >> 4; int l = j & 15;
        float acc = 0.f;
        #pragma unroll 8
        for (int gg = 0; gg < G; gg++) acc += sv[x * G + gg] * nv_w[gg * LG + l];
        g_nv[(size_t)n * 48 + j] = acc;
    } else {
        int j = t - 64;  // 0..63: 16 scalar acc + 48 vector acc
        if (j < LG) g_acc_s[(size_t)n * LG + j] = 0.f;
        else        g_acc_v[(size_t)n * 48 + (j - LG)] = 0.f;
    }
    __syncthreads();

    if (t < LG) {
        float acc = 0.f;
        #pragma unroll
        for (int k = 0; k < LG; k++) acc += sns[k] * en_w[k * LG + t];
        g_a[(size_t)n * LG + t] = acc;
    } else if (t < 2 * LG) {
        int j = t - LG;
        float acc = en_b[j];
        #pragma unroll
        for (int k = 0; k < LG; k++) acc += sns[k] * en_w[(LG + k) * LG + j];
        g_b[(size_t)n * LG + j] = acc;
    }
}

// ============================================================================
// Kernel 2: per-edge fused chain. One thread per edge, weights in SMEM.
// ============================================================================
__global__ void __launch_bounds__(128) k_edge(
    const float* __restrict__ edge_s, const float* __restrict__ edge_v,
    const float* __restrict__ dist,   const float* __restrict__ vctr,
    const int* __restrict__ src,      const int* __restrict__ dst,
    const float* __restrict__ tp_w, const float* __restrict__ tp_b,
    const float* __restrict__ g1w,  const float* __restrict__ g1b,
    const float* __restrict__ g2w,  const float* __restrict__ g2b,
    const float* __restrict__ tvw,  const float* __restrict__ tvb,
    float* __restrict__ out_es, float* __restrict__ out_ev)
{
    __shared__ float s_tp[LG * LG], s_g1[LG * LG], s_g2[LG * LG], s_tv[LG * 48];
    __shared__ float s_tpb[LG], s_g1b[LG], s_g2b[LG], s_tvb[48];
    int t = threadIdx.x;
    for (int i = t; i < 256; i += 128) { s_tp[i] = tp_w[i]; s_g1[i] = g1w[i]; s_g2[i] = g2w[i]; }
    for (int i = t; i < 768; i += 128) s_tv[i] = tvw[i];
    if (t < 16) { s_tpb[t] = tp_b[t]; s_g1b[t] = g1b[t]; s_g2b[t] = g2b[t]; }
    if (t < 48) s_tvb[t] = tvb[t];
    __syncthreads();

    int e = blockIdx.x * 128 + t;
    if (e >= N_EDGES) return;

    int s = src[e], d = dst[e];

    // edge_s row (vectorized)
    float esl[16];
    {
        const float4* p = (const float4*)(edge_s + (size_t)e * 16);
        #pragma unroll
        for (int i = 0; i < 4; i++) {
            float4 v = p[i];
            esl[4 * i] = v.x; esl[4 * i + 1] = v.y; esl[4 * i + 2] = v.z; esl[4 * i + 3] = v.w;
        }
    }

    // edge_neighbors = a[src] + b[dst]  (en_b already folded into b)
    float en[16];
    {
        const float4* pa = (const float4*)(g_a + (size_t)s * 16);
        const float4* pb = (const float4*)(g_b + (size_t)d * 16);
        #pragma unroll
        for (int i = 0; i < 4; i++) {
            float4 va = pa[i], vb = pb[i];
            en[4 * i]     = va.x + vb.x; en[4 * i + 1] = va.y + vb.y;
            en[4 * i + 2] = va.z + vb.z; en[4 * i + 3] = va.w + vb.w;
        }
    }

    // triplet_message = en * (edge_s @ tp_w + tp_b)
    float tm[16];
    #pragma unroll
    for (int j = 0; j < 16; j++) tm[j] = s_tpb[j];
    #pragma unroll
    for (int k = 0; k < 16; k++) {
        float x = esl[k];
        #pragma unroll
        for (int j = 0; j < 16; j++) tm[j] += x * s_tp[k * 16 + j];
    }
    #pragma unroll
    for (int j = 0; j < 16; j++) tm[j] *= en[j];

    // gate = sigmoid(silu(tm @ g1 + b1) @ g2 + b2)
    float h[16];
    #pragma unroll
    for (int j = 0; j < 16; j++) h[j] = s_g1b[j];
    #pragma unroll
    for (int k = 0; k < 16; k++) {
        float x = tm[k];
        #pragma unroll
        for (int j = 0; j < 16; j++) h[j] += x * s_g1[k * 16 + j];
    }
    #pragma unroll
    for (int j = 0; j < 16; j++) h[j] = siluf(h[j]);

    float gt[16];
    #pragma unroll
    for (int j = 0; j < 16; j++) gt[j] = s_g2b[j];
    #pragma unroll
    for (int k = 0; k < 16; k++) {
        float x = h[k];
        #pragma unroll
        for (int j = 0; j < 16; j++) gt[j] += x * s_g2[k * 16 + j];
    }

    float dd = dist[e];
    float C = 0.5f * (cosf(PI_F * dd * 0.1f) + 1.f) * (dd < 10.f ? 1.f : 0.f);

    float es[16];
    #pragma unroll
    for (int j = 0; j < 16; j++) es[j] = tm[j] * (1.f / (1.f + __expf(-gt[j]))) * C;

    // edge_s_out = es + edge_s ; scatter es to acc_s[dst]
    {
        float4* po = (float4*)(out_es + (size_t)e * 16);
        #pragma unroll
        for (int i = 0; i < 4; i++) {
            float4 v;
            v.x = es[4 * i]     + esl[4 * i];
            v.y = es[4 * i + 1] + esl[4 * i + 1];
            v.z = es[4 * i + 2] + esl[4 * i + 2];
            v.w = es[4 * i + 3] + esl[4 * i + 3];
            po[i] = v;
        }
        float* pacc = g_acc_s + (size_t)d * 16;
        #pragma unroll
        for (int i = 0; i < 4; i++)
            red4(pacc + 4 * i, es[4 * i], es[4 * i + 1], es[4 * i + 2], es[4 * i + 3]);
    }

    // vec_ch = es @ tv_w + tv_b -> t/e/r channels, pre-scaled by C
    float ter[48];
    #pragma unroll
    for (int j = 0; j < 48; j++) ter[j] = s_tvb[j];
    #pragma unroll
    for (int k = 0; k < 16; k++) {
        float x = es[k];
        #pragma unroll
        for (int j = 0; j < 48; j++) ter[j] += x * s_tv[k * 48 + j];
    }
    #pragma unroll
    for (int j = 0; j < 48; j++) ter[j] *= C;

    float vn0 = vctr[(size_t)e * 3];
    float vn1 = vctr[(size_t)e * 3 + 1];
    float vn2 = vctr[(size_t)e * 3 + 2];

    #pragma unroll
    for (int x = 0; x < 3; x++) {
        float vnx = (x == 0) ? vn0 : (x == 1) ? vn1 : vn2;
        float evi[16], nvs[16];
        {
            const float4* pe = (const float4*)(edge_v + (size_t)e * 48 + x * 16);
            const float4* pn = (const float4*)(g_nv + (size_t)s * 48 + x * 16);
            #pragma unroll
            for (int i = 0; i < 4; i++) {
                float4 a = pe[i], b = pn[i];
                evi[4 * i] = a.x; evi[4 * i + 1] = a.y; evi[4 * i + 2] = a.z; evi[4 * i + 3] = a.w;
                nvs[4 * i] = b.x; nvs[4 * i + 1] = b.y; nvs[4 * i + 2] = b.z; nvs[4 * i + 3] = b.w;
            }
        }
        float evu[16];
        #pragma unroll
        for (int j = 0; j < 16; j++)
            evu[j] = evi[j] * ter[j] + nvs[j] * ter[16 + j] + vnx * ter[32 + j];

        float4* po = (float4*)(out_ev + (size_t)e * 48 + x * 16);
        #pragma unroll
        for (int i = 0; i < 4; i++) {
            float4 v;
            v.x = evu[4 * i]     + evi[4 * i];
            v.y = evu[4 * i + 1] + evi[4 * i + 1];
            v.z = evu[4 * i + 2] + evi[4 * i + 2];
            v.w = evu[4 * i + 3] + evi[4 * i + 3];
            po[i] = v;
        }
        float* pacc = g_acc_v + (size_t)d * 48 + x * 16;
        #pragma unroll
        for (int i = 0; i < 4; i++)
            red4(pacc + 4 * i, evu[4 * i], evu[4 * i + 1], evu[4 * i + 2], evu[4 * i + 3]);
    }
}

// ============================================================================
// Kernel 3: per-node epilogue. One block (128 threads) per node; t = g-channel.
// ============================================================================
__global__ void __launch_bounds__(128) k_node_out(
    const float* __restrict__ node_s, const float* __restrict__ node_v,
    const float* __restrict__ onw,
    const float* __restrict__ w1, const float* __restrict__ b1,
    const float* __restrict__ w2, const float* __restrict__ b2,
    const float* __restrict__ gamma, const float* __restrict__ beta,
    const float* __restrict__ cns, float* __restrict__ out)
{
    int n = blockIdx.x;
    int t = threadIdx.x;  // 128
    __shared__ float sacc[16], snvn[16], sh[16], saccv[48];
    __shared__ float rs1[4], rs2[4];

    if (t < 16) sacc[t] = g_acc_s[(size_t)n * 16 + t];
    else if (t < 64) saccv[t - 16] = g_acc_v[(size_t)n * 48 + (t - 16)];
    else if (t < 80) {
        int l = t - 64;
        float a = g_nv[(size_t)n * 48 + l];
        float b = g_nv[(size_t)n * 48 + 16 + l];
        float c = g_nv[(size_t)n * 48 + 32 + l];
        snvn[l] = sqrtf(a * a + b * b + c * c);
    }
    __syncthreads();

    if (t < 16) {
        float acc = b1[t];
        #pragma unroll
        for (int k = 0; k < 16; k++) acc += sacc[k] * w1[k * 16 + t];
        #pragma unroll
        for (int k = 0; k < 16; k++) acc += snvn[k] * w1[(16 + k) * 16 + t];
        sh[t] = siluf(acc);
    }
    __syncthreads();

    // n_s_upd channel t
    float nsu = b2[t];
    #pragma unroll
    for (int l = 0; l < 16; l++) nsu += sh[l] * w2[l * 128 + t];
    float xv = nsu + node_s[(size_t)n * 128 + t];

    // block reduce for mean/var
    float s1 = xv, s2 = xv * xv;
    #pragma unroll
    for (int o = 16; o > 0; o >>= 1) {
        s1 += __shfl_down_sync(0xffffffffu, s1, o);
        s2 += __shfl_down_sync(0xffffffffu, s2, o);
    }
    if ((t & 31) == 0) { rs1[t >> 5] = s1; rs2[t >> 5] = s2; }
    __syncthreads();
    float ts1 = rs1[0] + rs1[1] + rs1[2] + rs1[3];
    float ts2 = rs2[0] + rs2[1] + rs2[2] + rs2[3];
    float mu = ts1 * (1.f / 128.f);
    float var = ts2 * (1.f / 128.f) - mu * mu;
    float outs = (xv - mu) * rsqrtf(var + 1e-5f) * gamma[t] + beta[t];
    out[(size_t)n * 128 + t] = outs;

    // vector channels
    float v0, v1, v2;
    {
        float a0 = 0.f, a1 = 0.f, a2 = 0.f;
        #pragma unroll
        for (int l = 0; l < 16; l++) {
            float w = onw[l * 128 + t];
            a0 += saccv[l] * w;
            a1 += saccv[16 + l] * w;
            a2 += saccv[32 + l] * w;
        }
        v0 = a0 + node_v[(size_t)n * 384 + t];
        v1 = a1 + node_v[(size_t)n * 384 + 128 + t];
        v2 = a2 + node_v[(size_t)n * 384 + 256 + t];
    }
    float vn = sqrtf(v0 * v0 + v1 * v1 + v2 * v2);
    float sc = cns[t] / (vn + 1e-8f);
    size_t base = 6400000ull + (size_t)n * 384;
    out[base + t]       = v0 * sc;
    out[base + 128 + t] = v1 * sc;
    out[base + 256 + t] = v2 * sc;
}

// ============================================================================
extern "C" void kernel_launch(void* const* d_in, const int* in_sizes, int n_in,
                              void* d_out, int out_size)
{
    const float* node_s  = (const float*)d_in[0];
    const float* node_v  = (const float*)d_in[1];
    const float* edge_s  = (const float*)d_in[2];
    const float* edge_v  = (const float*)d_in[3];
    const float* dist    = (const float*)d_in[4];
    const float* vctr    = (const float*)d_in[5];
    const int*   src     = (const int*)d_in[6];
    const int*   dst     = (const int*)d_in[7];
    const float* ns_in_w = (const float*)d_in[8];
    const float* ns_in_b = (const float*)d_in[9];
    const float* nv_in_w = (const float*)d_in[10];
    const float* en_w    = (const float*)d_in[11];
    const float* en_b    = (const float*)d_in[12];
    const float* tp_w    = (const float*)d_in[13];
    const float* tp_b    = (const float*)d_in[14];
    const float* gate_w1 = (const float*)d_in[15];
    const float* gate_b1 = (const float*)d_in[16];
    const float* gate_w2 = (const float*)d_in[17];
    const float* gate_b2 = (const float*)d_in[18];
    const float* tv_w    = (const float*)d_in[19];
    const float* tv_b    = (const float*)d_in[20];
    const float* out_nv_w= (const float*)d_in[21];
    const float* ons_w1  = (const float*)d_in[22];
    const float* ons_b1  = (const float*)d_in[23];
    const float* ons_w2  = (const float*)d_in[24];
    const float* ons_b2  = (const float*)d_in[25];
    const float* ln_gamma= (const float*)d_in[26];
    const float* ln_beta = (const float*)d_in[27];
    const float* cn_scale= (const float*)d_in[28];

    float* out = (float*)d_out;
    // output layout: node_s_out [0, 6.4M), node_v_out [6.4M, 25.6M),
    //                edge_s_out [25.6M, 51.2M), edge_v_out [51.2M, 128M)
    float* out_es = out + 25600000ull;
    float* out_ev = out + 51200000ull;

    k_node_in<<<N_NODES, 128>>>(node_s, node_v, ns_in_w, ns_in_b, nv_in_w, en_w, en_b);
    k_edge<<<N_EDGES / 128, 128>>>(edge_s, edge_v, dist, vctr, src, dst,
                                   tp_w, tp_b, gate_w1, gate_b1, gate_w2, gate_b2,
                                   tv_w, tv_b, out_es, out_ev);
    k_node_out<<<N_NODES, 128>>>(node_s, node_v, out_nv_w, ons_w1, ons_b1,
                                 ons_w2, ons_b2, ln_gamma, ln_beta, cn_scale, out);
}